// round 13
// baseline (speedup 1.0000x reference)
#include <cuda_runtime.h>
#include <cuda_bf16.h>
#include <cstdint>

#define B_      64
#define SSTATE  512
#define SSEQ    2048
#define HDIM    512
#define MTOT    (B_*SSTATE)
#define NCHUNK  16          // K = 512 in chunks of 32
#define NSTAGE  4

#if defined(__CUDA_ARCH_FEAT_SM103_ALL) || defined(__CUDA_ARCH_FEAT_SM100_ALL) || defined(__CUDA_ARCH_SPECIFIC__)
#define TCGEN05_OK 1
#else
#define TCGEN05_OK 0
#endif

// idesc kind::f16 bf16 x bf16 -> fp32, M=128, N=256
#define IDESC_128x256 \
    ((1u << 4) | (1u << 7) | (1u << 10) | ((256u / 8) << 17) | ((128u / 16) << 24))

// scratch (static device globals)
__device__ __nv_bfloat16 g_Qhi[(size_t)MTOT * HDIM];
__device__ __nv_bfloat16 g_Qlo[(size_t)MTOT * HDIM];
__device__ __nv_bfloat16 g_Shi[(size_t)MTOT * HDIM];
__device__ __nv_bfloat16 g_Slo[(size_t)MTOT * HDIM];
__device__ __nv_bfloat16 g_Wth[HDIM * HDIM];
__device__ __nv_bfloat16 g_Wtl[HDIM * HDIM];

// ---- split helpers (truncate-hi + exact remainder) ----
__device__ __forceinline__ uint32_t pack_hi2(float x0, float x1) {
    return (__float_as_uint(x0) >> 16) | (__float_as_uint(x1) & 0xFFFF0000u);
}
__device__ __forceinline__ uint32_t pack_lo2(float x0, float x1) {
    float r0 = x0 - __uint_as_float(__float_as_uint(x0) & 0xFFFF0000u);
    float r1 = x1 - __uint_as_float(__float_as_uint(x1) & 0xFFFF0000u);
    uint32_t r;
    asm("cvt.rn.bf16x2.f32 %0, %1, %2;" : "=r"(r) : "f"(r1), "f"(r0));
    return r;
}

#if TCGEN05_OK
__device__ __forceinline__ uint32_t smem_u32(const void* p) {
    uint32_t a;
    asm("{ .reg .u64 t; cvta.to.shared.u64 t, %1; cvt.u32.u64 %0, t; }" : "=r"(a) : "l"(p));
    return a;
}
__device__ __forceinline__ uint32_t elect_one() {
    uint32_t p;
    asm volatile("{ .reg .pred p; elect.sync _|p, 0xFFFFFFFF; selp.b32 %0,1,0,p; }" : "=r"(p));
    return p;
}
// SW64 descriptor: layout=4, Blackwell version=1, SBO=32, LBO=1 (HW-verified R10/R11)
__device__ __forceinline__ uint64_t make_desc64(uint32_t addr) {
    const uint64_t base = (uint64_t(4) << 61) | (uint64_t(1) << 46) |
                          (uint64_t(32) << 32) | (uint64_t(1) << 16);
    return base | ((uint64_t)(addr >> 4) & 0x3FFF);
}
__device__ __forceinline__ void mma_ss_f16(uint32_t d, uint64_t a, uint64_t b,
                                           uint32_t idesc, uint32_t en) {
    asm volatile(
        "{\n\t.reg .pred p;\n\tsetp.ne.u32 p, %4, 0;\n\t"
        "tcgen05.mma.cta_group::1.kind::f16 [%0], %1, %2, %3, {%5,%5,%5,%5}, p;\n\t}"
        :: "r"(d), "l"(a), "l"(b), "r"(idesc), "r"(en), "r"(0u) : "memory");
}

#define CPA16(dst_u32, src_ptr) \
    asm volatile("cp.async.cg.shared.global [%0], [%1], 16;" \
                 :: "r"(dst_u32), "l"(src_ptr) : "memory")
#define CPA_COMMIT()  asm volatile("cp.async.commit_group;" ::: "memory")
#define CPA_WAIT(n)   asm volatile("cp.async.wait_group %0;" :: "n"(n) : "memory")

#define MBAR_INIT(addr, cnt) \
    asm volatile("mbarrier.init.shared.b64 [%0], %1;" :: "r"(addr), "r"(cnt) : "memory")
#define MBAR_WAIT(addr, phv) do {                                                   \
    uint32_t _m = (addr), _p = (uint32_t)(phv), _d;                                 \
    asm volatile("{\n\t.reg .pred p;\n\t"                                           \
        "mbarrier.try_wait.parity.acquire.cta.shared::cta.b64 p, [%1], %2;\n\t"     \
        "selp.b32 %0,1,0,p;\n\t}" : "=r"(_d) : "r"(_m), "r"(_p) : "memory");        \
    if (!_d) {                                                                      \
        asm volatile("{\n\t.reg .pred P1;\n\t"                                      \
        "WL_%=:\n\t"                                                                \
        "mbarrier.try_wait.parity.acquire.cta.shared::cta.b64 P1, [%0], %1, 0x989680;\n\t" \
        "@P1 bra.uni WD_%=;\n\t"                                                    \
        "bra.uni WL_%=;\n\t"                                                        \
        "WD_%=:\n\t}" :: "r"(_m), "r"(_p) : "memory");                              \
    } } while (0)

#define LD32X32(r, ta)                                                              \
    asm volatile("tcgen05.ld.sync.aligned.32x32b.x32.b32 "                          \
        "{%0, %1, %2, %3, %4, %5, %6, %7, %8, %9, %10, %11, %12, %13, %14, %15, "   \
        " %16, %17, %18, %19, %20, %21, %22, %23, %24, %25, %26, %27, %28, %29, %30, %31}, [%32];" \
        : "=r"((r)[0]),"=r"((r)[1]),"=r"((r)[2]),"=r"((r)[3]),                      \
          "=r"((r)[4]),"=r"((r)[5]),"=r"((r)[6]),"=r"((r)[7]),                      \
          "=r"((r)[8]),"=r"((r)[9]),"=r"((r)[10]),"=r"((r)[11]),                    \
          "=r"((r)[12]),"=r"((r)[13]),"=r"((r)[14]),"=r"((r)[15]),                  \
          "=r"((r)[16]),"=r"((r)[17]),"=r"((r)[18]),"=r"((r)[19]),                  \
          "=r"((r)[20]),"=r"((r)[21]),"=r"((r)[22]),"=r"((r)[23]),                  \
          "=r"((r)[24]),"=r"((r)[25]),"=r"((r)[26]),"=r"((r)[27]),                  \
          "=r"((r)[28]),"=r"((r)[29]),"=r"((r)[30]),"=r"((r)[31])                   \
        : "r"(ta))

#define SWZ64(o) ((o) ^ (((o) >> 3) & 0x30))
#endif  // TCGEN05_OK

// Stage (K=32): Ahi 8K | Alo 8K | Bhi 16K | Blo 16K = 48K; 4 stages = 192K.
#define STG_BYTES   49152
#define A_LO_OFF    8192
#define B_HI_OFF    16384
#define B_LO_OFF    32768
#define SMEM_DYN    (2048 + NSTAGE*STG_BYTES)

// ---------------------------------------------------------------------------
// W transpose + split
// ---------------------------------------------------------------------------
__global__ __launch_bounds__(256)
void wt_kernel(const float* __restrict__ W) {
    __shared__ float t[32][33];
    int h0 = blockIdx.y * 32, d0 = blockIdx.x * 32;
    int x = threadIdx.x & 31, y = threadIdx.x >> 5;
#pragma unroll
    for (int i = 0; i < 32; i += 8)
        t[y + i][x] = W[(size_t)(h0 + y + i) * HDIM + d0 + x];
    __syncthreads();
#pragma unroll
    for (int i = 0; i < 32; i += 8) {
        float v = t[x][y + i];
        uint32_t u = __float_as_uint(v);
        size_t off = (size_t)(d0 + y + i) * HDIM + h0 + x;
        g_Wth[off] = __ushort_as_bfloat16((unsigned short)(u >> 16));
        g_Wtl[off] = __float2bfloat16(v - __uint_as_float(u & 0xFFFF0000u));
    }
}

// ---------------------------------------------------------------------------
// S fp32 -> bf16 hi/lo split (HBM-bound, small)
// ---------------------------------------------------------------------------
__global__ __launch_bounds__(256)
void split_s_kernel(const float* __restrict__ S) {
    size_t base = ((size_t)blockIdx.x * 256 + threadIdx.x) * 8;
    float4 a = *(const float4*)(S + base);
    float4 b = *(const float4*)(S + base + 4);
    uint4 hi, lo;
    hi.x = pack_hi2(a.x, a.y); hi.y = pack_hi2(a.z, a.w);
    hi.z = pack_hi2(b.x, b.y); hi.w = pack_hi2(b.z, b.w);
    lo.x = pack_lo2(a.x, a.y); lo.y = pack_lo2(a.z, a.w);
    lo.z = pack_lo2(b.x, b.y); lo.w = pack_lo2(b.z, b.w);
    *(uint4*)((char*)g_Shi + base * 2) = hi;
    *(uint4*)((char*)g_Slo + base * 2) = lo;
}

#if TCGEN05_OK
// ---------------------------------------------------------------------------
// K1 mainloop (both operands pre-split, pure cp.async) — unchanged from R11.
// ---------------------------------------------------------------------------
__device__ __forceinline__ uint32_t gemm_mainloop(
    uint32_t sb, uint32_t db,
    const __nv_bfloat16* ahi, const __nv_bfloat16* alo, size_t arow0,
    const __nv_bfloat16* bhi, const __nv_bfloat16* blo, size_t brow0) {
    int tid = threadIdx.x, wid = tid >> 5;

    if (wid == 0)
        asm volatile("tcgen05.alloc.cta_group::1.sync.aligned.shared::cta.b32 [%0], %1;"
                     :: "r"(sb + 32), "r"(256u) : "memory");
    if (tid == 0) {
#pragma unroll
        for (int s = 0; s < NSTAGE; s++) MBAR_INIT(sb + s * 8, 1u);
    }
    __syncthreads();
    uint32_t td;
    asm volatile("ld.shared.b32 %0, [%1];" : "=r"(td) : "r"(sb + 32));

    auto load_chunk = [&](int c) {
        uint32_t ba = db + (c & 3) * STG_BYTES;
        int k0 = c * 32;
#pragma unroll
        for (int t = 0; t < 2; t++) {
            int it = tid + 256 * t;
            int r = it >> 2, g = it & 3;
            int o = SWZ64(r * 64 + g * 16);
            size_t src = (arow0 + r) * HDIM + k0 + (g << 3);
            CPA16(ba + o,            ahi + src);
            CPA16(ba + A_LO_OFF + o, alo + src);
        }
#pragma unroll
        for (int t = 0; t < 4; t++) {
            int it = tid + 256 * t;
            int r = it >> 2, g = it & 3;
            int o = SWZ64(r * 64 + g * 16);
            size_t src = (brow0 + r) * HDIM + k0 + (g << 3);
            CPA16(ba + B_HI_OFF + o, bhi + src);
            CPA16(ba + B_LO_OFF + o, blo + src);
        }
        CPA_COMMIT();
    };

    load_chunk(0);
    load_chunk(1);
    load_chunk(2);

#pragma unroll
    for (int c = 0; c < NCHUNK; c++) {
        if (c <= 13)      CPA_WAIT(2);
        else if (c == 14) CPA_WAIT(1);
        else              CPA_WAIT(0);
        asm volatile("fence.proxy.async.shared::cta;" ::: "memory");
        __syncthreads();
        if (wid == 0 && elect_one()) {
            uint32_t ba = db + (c & 3) * STG_BYTES;
            uint64_t ah = make_desc64(ba), al = make_desc64(ba + A_LO_OFF);
            uint64_t bh = make_desc64(ba + B_HI_OFF), bl = make_desc64(ba + B_LO_OFF);
#pragma unroll
            for (int ks = 0; ks < 2; ks++)
                mma_ss_f16(td, ah + 2 * ks, bh + 2 * ks, IDESC_128x256,
                           (c == 0 && ks == 0) ? 0u : 1u);
#pragma unroll
            for (int ks = 0; ks < 2; ks++)
                mma_ss_f16(td, ah + 2 * ks, bl + 2 * ks, IDESC_128x256, 1u);
#pragma unroll
            for (int ks = 0; ks < 2; ks++)
                mma_ss_f16(td, al + 2 * ks, bh + 2 * ks, IDESC_128x256, 1u);
            asm volatile(
                "tcgen05.commit.cta_group::1.mbarrier::arrive::one.shared::cluster.b64 [%0];"
                :: "r"(sb + (c & 3) * 8) : "memory");
        }
        if (c + 3 < NCHUNK) {
            if (c >= 1)
                MBAR_WAIT(sb + ((c - 1) & 3) * 8, ((c - 1) >> 2) & 1);
            load_chunk(c + 3);
        }
    }
    MBAR_WAIT(sb + 3 * 8, 1);
    asm volatile("tcgen05.fence::after_thread_sync;" ::: "memory");
    return td;
}

// ---------------------------------------------------------------------------
// K2 mainloop: A = pre-split Q (cp.async); B = fp32 history, LDG-prefetched
// 2 chunks ahead into ping-pong registers, converted + STS'd at use time.
// ---------------------------------------------------------------------------
__device__ __forceinline__ uint32_t k2_mainloop(
    uint32_t sb, uint32_t db, char* dp,
    const __nv_bfloat16* ahi, const __nv_bfloat16* alo, size_t arow0,
    const float* __restrict__ Bf, size_t brow0) {
    int tid = threadIdx.x, wid = tid >> 5;

    if (wid == 0)
        asm volatile("tcgen05.alloc.cta_group::1.sync.aligned.shared::cta.b32 [%0], %1;"
                     :: "r"(sb + 32), "r"(256u) : "memory");
    if (tid == 0) {
#pragma unroll
        for (int s = 0; s < NSTAGE; s++) MBAR_INIT(sb + s * 8, 1u);
    }
    __syncthreads();
    uint32_t td;
    asm volatile("ld.shared.b32 %0, [%1];" : "=r"(td) : "r"(sb + 32));

    auto load_a = [&](int c) {
        uint32_t ba = db + (c & 3) * STG_BYTES;
        int k0 = c * 32;
#pragma unroll
        for (int t = 0; t < 2; t++) {
            int it = tid + 256 * t;
            int r = it >> 2, g = it & 3;
            int o = SWZ64(r * 64 + g * 16);
            size_t src = (arow0 + r) * HDIM + k0 + (g << 3);
            CPA16(ba + o,            ahi + src);
            CPA16(ba + A_LO_OFF + o, alo + src);
        }
        CPA_COMMIT();
    };
    // LDG chunk c of fp32 B into regs: 8 float4 per thread (row r, 4-col group g)
    auto ldg_b = [&](int c, float4* v) {
        int k0 = c * 32;
#pragma unroll
        for (int q = 0; q < 8; q++) {
            int idx = tid + 256 * q;
            int r = idx >> 3, g = idx & 7;
            v[q] = *(const float4*)(Bf + (brow0 + r) * HDIM + k0 + (g << 2));
        }
    };
    // convert regs -> hi/lo STS.64 into stage c&3
    auto sts_b = [&](int c, const float4* v) {
        char* st = dp + (c & 3) * STG_BYTES;
#pragma unroll
        for (int q = 0; q < 8; q++) {
            int idx = tid + 256 * q;
            int r = idx >> 3, g = idx & 7;
            int o = SWZ64(r * 64 + g * 8);
            uint2 hi, lo;
            hi.x = pack_hi2(v[q].x, v[q].y); hi.y = pack_hi2(v[q].z, v[q].w);
            lo.x = pack_lo2(v[q].x, v[q].y); lo.y = pack_lo2(v[q].z, v[q].w);
            *(uint2*)(st + B_HI_OFF + o) = hi;
            *(uint2*)(st + B_LO_OFF + o) = lo;
        }
    };

    float4 bs0[8], bs1[8];          // ping-pong register sets (even/odd chunks)
    ldg_b(0, bs0);
    ldg_b(1, bs1);
    load_a(0);
    load_a(1);
    load_a(2);

#pragma unroll
    for (int c = 0; c < NCHUNK; c++) {
        sts_b(c, (c & 1) ? bs1 : bs0);
        if (c <= 13)      CPA_WAIT(2);
        else if (c == 14) CPA_WAIT(1);
        else              CPA_WAIT(0);
        asm volatile("fence.proxy.async.shared::cta;" ::: "memory");
        __syncthreads();
        if (wid == 0 && elect_one()) {
            uint32_t ba = db + (c & 3) * STG_BYTES;
            uint64_t ah = make_desc64(ba), al = make_desc64(ba + A_LO_OFF);
            uint64_t bh = make_desc64(ba + B_HI_OFF), bl = make_desc64(ba + B_LO_OFF);
#pragma unroll
            for (int ks = 0; ks < 2; ks++)
                mma_ss_f16(td, ah + 2 * ks, bh + 2 * ks, IDESC_128x256,
                           (c == 0 && ks == 0) ? 0u : 1u);
#pragma unroll
            for (int ks = 0; ks < 2; ks++)
                mma_ss_f16(td, ah + 2 * ks, bl + 2 * ks, IDESC_128x256, 1u);
#pragma unroll
            for (int ks = 0; ks < 2; ks++)
                mma_ss_f16(td, al + 2 * ks, bh + 2 * ks, IDESC_128x256, 1u);
            asm volatile(
                "tcgen05.commit.cta_group::1.mbarrier::arrive::one.shared::cluster.b64 [%0];"
                :: "r"(sb + (c & 3) * 8) : "memory");
        }
        if (c + 2 < NCHUNK) ldg_b(c + 2, (c & 1) ? bs1 : bs0);
        if (c + 3 < NCHUNK) {
            if (c >= 1)
                MBAR_WAIT(sb + ((c - 1) & 3) * 8, ((c - 1) >> 2) & 1);
            load_a(c + 3);
        }
    }
    MBAR_WAIT(sb + 3 * 8, 1);
    asm volatile("tcgen05.fence::after_thread_sync;" ::: "memory");
    return td;
}

__device__ __forceinline__ void gemm_cleanup(uint32_t td) {
    __syncthreads();
    if ((threadIdx.x >> 5) == 0)
        asm volatile("tcgen05.dealloc.cta_group::1.sync.aligned.b32 %0, %1;"
                     :: "r"(td), "r"(256u));
}
#endif  // TCGEN05_OK

// ---------------------------------------------------------------------------
// K1: Q = S @ W, epilogue -> Q hi/lo bf16
// ---------------------------------------------------------------------------
__global__ __launch_bounds__(256, 1)
void k1_kernel() {
#if TCGEN05_OK
    extern __shared__ char sm[];
    uint32_t sb = smem_u32(sm);
    uint32_t db = (sb + 64 + 1023) & ~1023u;
    int wid = threadIdx.x >> 5, lane = threadIdx.x & 31;
    int m0 = blockIdx.y * 128, n0 = blockIdx.x * 256;

    uint32_t td = gemm_mainloop(sb, db, g_Shi, g_Slo, (size_t)m0,
                                g_Wth, g_Wtl, (size_t)n0);

    int mrow = m0 + ((wid & 3) << 5) + lane;
    int cb = (wid >> 2) * 128;
#pragma unroll
    for (int itn = 0; itn < 4; itn++) {
        uint32_t dr[32];
        LD32X32(dr, td + cb + itn * 32);
        asm volatile("tcgen05.wait::ld.sync.aligned;" ::: "memory");
#pragma unroll
        for (int g = 0; g < 4; g++) {
            float q0 = __uint_as_float(dr[g * 8 + 0]), q1 = __uint_as_float(dr[g * 8 + 1]);
            float q2 = __uint_as_float(dr[g * 8 + 2]), q3 = __uint_as_float(dr[g * 8 + 3]);
            float q4 = __uint_as_float(dr[g * 8 + 4]), q5 = __uint_as_float(dr[g * 8 + 5]);
            float q6 = __uint_as_float(dr[g * 8 + 6]), q7 = __uint_as_float(dr[g * 8 + 7]);
            uint4 hi, lo;
            hi.x = pack_hi2(q0, q1); hi.y = pack_hi2(q2, q3);
            hi.z = pack_hi2(q4, q5); hi.w = pack_hi2(q6, q7);
            lo.x = pack_lo2(q0, q1); lo.y = pack_lo2(q2, q3);
            lo.z = pack_lo2(q4, q5); lo.w = pack_lo2(q6, q7);
            size_t off = (size_t)mrow * HDIM + n0 + cb + itn * 32 + g * 8;
            *(uint4*)(g_Qhi + off) = hi;
            *(uint4*)(g_Qlo + off) = lo;
        }
    }
    gemm_cleanup(td);
#endif
}

// ---------------------------------------------------------------------------
// K2: E[b] = Q[b] @ hist[b]^T  (B = fp32 history, reg-converted in-kernel)
// ---------------------------------------------------------------------------
__global__ __launch_bounds__(256, 1)
void k2_kernel(const float* __restrict__ Hst, float* __restrict__ out) {
#if TCGEN05_OK
    extern __shared__ char sm[];
    uint32_t sb = smem_u32(sm);
    uint32_t db = (sb + 64 + 1023) & ~1023u;
    char* dp = sm + (db - sb);
    int wid = threadIdx.x >> 5, lane = threadIdx.x & 31;
    int bb = blockIdx.z;
    int m0 = blockIdx.y * 128, n0 = blockIdx.x * 256;
    float* C = out + (size_t)bb * SSTATE * SSEQ;

    uint32_t td = k2_mainloop(sb, db, dp,
                              g_Qhi, g_Qlo, (size_t)bb * SSTATE + m0,
                              Hst, (size_t)bb * SSEQ + n0);

    int mloc = ((wid & 3) << 5) + lane;
    int cb = (wid >> 2) * 128;
#pragma unroll
    for (int itn = 0; itn < 4; itn++) {
        uint32_t dr[32];
        LD32X32(dr, td + cb + itn * 32);
        asm volatile("tcgen05.wait::ld.sync.aligned;" ::: "memory");
        float* crow = C + (size_t)(m0 + mloc) * SSEQ + n0 + cb + itn * 32;
#pragma unroll
        for (int g = 0; g < 8; g++) {
            *(float4*)(crow + g * 4) = make_float4(
                __uint_as_float(dr[g * 4 + 0]), __uint_as_float(dr[g * 4 + 1]),
                __uint_as_float(dr[g * 4 + 2]), __uint_as_float(dr[g * 4 + 3]));
        }
    }
    gemm_cleanup(td);
#endif
}

// ---------------------------------------------------------------------------
// softmax over rows of 2048 (75% of HBM peak — unchanged)
// ---------------------------------------------------------------------------
__device__ __forceinline__ float fexp_neg(float x) {
    float t = x * 1.4426950408889634f;
    t = fmaxf(t, -250.0f);
    float fi = t + 12582912.0f;
    int i = __float_as_int(fi) - 0x4B400000;
    float f = t - (fi - 12582912.0f);
    float p = 1.5404e-4f;
    p = fmaf(p, f, 1.33336e-3f);
    p = fmaf(p, f, 9.61813e-3f);
    p = fmaf(p, f, 5.55041e-2f);
    p = fmaf(p, f, 2.40226513e-1f);
    p = fmaf(p, f, 6.93147182e-1f);
    p = fmaf(p, f, 1.0f);
    int i1 = i >> 1;
    int i2 = i - i1;
    return p * __int_as_float((i1 + 127) << 23) * __int_as_float((i2 + 127) << 23);
}

__global__ __launch_bounds__(256)
void softmax_kernel(float* __restrict__ data) {
    __shared__ float red[8];
    size_t row = blockIdx.x;
    float4* p = (float4*)(data + row * SSEQ);
    int tid = threadIdx.x;
    int lane = tid & 31, warp = tid >> 5;

    float4 v0 = p[tid];
    float4 v1 = p[tid + 256];
    float m = fmaxf(fmaxf(fmaxf(v0.x, v0.y), fmaxf(v0.z, v0.w)),
                    fmaxf(fmaxf(v1.x, v1.y), fmaxf(v1.z, v1.w)));
#pragma unroll
    for (int off = 16; off; off >>= 1) m = fmaxf(m, __shfl_xor_sync(0xffffffffu, m, off));
    if (lane == 0) red[warp] = m;
    __syncthreads();
    float gm = red[0];
#pragma unroll
    for (int w = 1; w < 8; w++) gm = fmaxf(gm, red[w]);
    __syncthreads();

    float e[8];
    e[0] = fexp_neg(v0.x - gm); e[1] = fexp_neg(v0.y - gm);
    e[2] = fexp_neg(v0.z - gm); e[3] = fexp_neg(v0.w - gm);
    e[4] = fexp_neg(v1.x - gm); e[5] = fexp_neg(v1.y - gm);
    e[6] = fexp_neg(v1.z - gm); e[7] = fexp_neg(v1.w - gm);
    float s = ((e[0] + e[1]) + (e[2] + e[3])) + ((e[4] + e[5]) + (e[6] + e[7]));
#pragma unroll
    for (int off = 16; off; off >>= 1) s += __shfl_xor_sync(0xffffffffu, s, off);
    if (lane == 0) red[warp] = s;
    __syncthreads();
    float gs = ((red[0] + red[1]) + (red[2] + red[3])) +
               ((red[4] + red[5]) + (red[6] + red[7]));
    float inv = 1.0f / gs;

    p[tid]       = make_float4(e[0] * inv, e[1] * inv, e[2] * inv, e[3] * inv);
    p[tid + 256] = make_float4(e[4] * inv, e[5] * inv, e[6] * inv, e[7] * inv);
}

// ---------------------------------------------------------------------------
extern "C" void kernel_launch(void* const* d_in, const int* in_sizes, int n_in,
                              void* d_out, int out_size) {
    (void)in_sizes; (void)n_in; (void)out_size;
    const float* S   = (const float*)d_in[0];  // out_state [64,512,512]
    const float* Hst = (const float*)d_in[1];  // history   [64,2048,512]
    const float* W   = (const float*)d_in[2];  // attn_w    [512,512]
    // d_in[3] (attn_b) unused: softmax is shift-invariant per row.
    float* out = (float*)d_out;                // [64,512,2048]

    cudaFuncSetAttribute(k1_kernel, cudaFuncAttributeMaxDynamicSharedMemorySize, SMEM_DYN);
    cudaFuncSetAttribute(k2_kernel, cudaFuncAttributeMaxDynamicSharedMemorySize, SMEM_DYN);

    wt_kernel<<<dim3(16, 16), 256>>>(W);
    split_s_kernel<<<(size_t)MTOT * HDIM / 2048, 256>>>(S);
    k1_kernel<<<dim3(HDIM / 256, MTOT / 128), 256, SMEM_DYN>>>();
    k2_kernel<<<dim3(SSEQ / 256, SSTATE / 128, B_), 256, SMEM_DYN>>>(Hst, out);
    softmax_kernel<<<MTOT, 256>>>(out);
}

// round 14
// speedup vs baseline: 1.4763x; 1.4763x over previous
#include <cuda_runtime.h>
#include <cuda_bf16.h>
#include <cstdint>

#define B_      64
#define SSTATE  512
#define SSEQ    2048
#define HDIM    512
#define MTOT    (B_*SSTATE)
#define NCHUNK  16          // K = 512 in chunks of 32
#define NSTAGE  3

#if defined(__CUDA_ARCH_FEAT_SM103_ALL) || defined(__CUDA_ARCH_FEAT_SM100_ALL) || defined(__CUDA_ARCH_SPECIFIC__)
#define TCGEN05_OK 1
#else
#define TCGEN05_OK 0
#endif

// idesc kind::f16 bf16 x bf16 -> fp32, M=128 (per dispatch), N=256
#define IDESC_128x256 \
    ((1u << 4) | (1u << 7) | (1u << 10) | ((256u / 8) << 17) | ((128u / 16) << 24))

// scratch (static device globals)
__device__ __nv_bfloat16 g_Qhi[(size_t)MTOT * HDIM];
__device__ __nv_bfloat16 g_Qlo[(size_t)MTOT * HDIM];
__device__ __nv_bfloat16 g_Shi[(size_t)MTOT * HDIM];
__device__ __nv_bfloat16 g_Slo[(size_t)MTOT * HDIM];
__device__ __nv_bfloat16 g_Hhi[(size_t)B_ * SSEQ * HDIM];
__device__ __nv_bfloat16 g_Hlo[(size_t)B_ * SSEQ * HDIM];
__device__ __nv_bfloat16 g_Wth[HDIM * HDIM];
__device__ __nv_bfloat16 g_Wtl[HDIM * HDIM];

// ---- split helpers (truncate-hi + exact remainder) ----
__device__ __forceinline__ uint32_t pack_hi2(float x0, float x1) {
    return (__float_as_uint(x0) >> 16) | (__float_as_uint(x1) & 0xFFFF0000u);
}
__device__ __forceinline__ uint32_t pack_lo2(float x0, float x1) {
    float r0 = x0 - __uint_as_float(__float_as_uint(x0) & 0xFFFF0000u);
    float r1 = x1 - __uint_as_float(__float_as_uint(x1) & 0xFFFF0000u);
    uint32_t r;
    asm("cvt.rn.bf16x2.f32 %0, %1, %2;" : "=r"(r) : "f"(r1), "f"(r0));
    return r;
}

#if TCGEN05_OK
__device__ __forceinline__ uint32_t smem_u32(const void* p) {
    uint32_t a;
    asm("{ .reg .u64 t; cvta.to.shared.u64 t, %1; cvt.u32.u64 %0, t; }" : "=r"(a) : "l"(p));
    return a;
}
__device__ __forceinline__ uint32_t elect_one() {
    uint32_t p;
    asm volatile("{ .reg .pred p; elect.sync _|p, 0xFFFFFFFF; selp.b32 %0,1,0,p; }" : "=r"(p));
    return p;
}
// SW64 descriptor: layout=4, Blackwell version=1, SBO=32, LBO=1 (HW-verified)
__device__ __forceinline__ uint64_t make_desc64(uint32_t addr) {
    const uint64_t base = (uint64_t(4) << 61) | (uint64_t(1) << 46) |
                          (uint64_t(32) << 32) | (uint64_t(1) << 16);
    return base | ((uint64_t)(addr >> 4) & 0x3FFF);
}
__device__ __forceinline__ void mma_ss_f16(uint32_t d, uint64_t a, uint64_t b,
                                           uint32_t idesc, uint32_t en) {
    asm volatile(
        "{\n\t.reg .pred p;\n\tsetp.ne.u32 p, %4, 0;\n\t"
        "tcgen05.mma.cta_group::1.kind::f16 [%0], %1, %2, %3, {%5,%5,%5,%5}, p;\n\t}"
        :: "r"(d), "l"(a), "l"(b), "r"(idesc), "r"(en), "r"(0u) : "memory");
}

#define CPA16(dst_u32, src_ptr) \
    asm volatile("cp.async.cg.shared.global [%0], [%1], 16;" \
                 :: "r"(dst_u32), "l"(src_ptr) : "memory")
#define CPA_COMMIT()  asm volatile("cp.async.commit_group;" ::: "memory")
#define CPA_WAIT(n)   asm volatile("cp.async.wait_group %0;" :: "n"(n) : "memory")

#define MBAR_INIT(addr, cnt) \
    asm volatile("mbarrier.init.shared.b64 [%0], %1;" :: "r"(addr), "r"(cnt) : "memory")
#define MBAR_WAIT(addr, phv) do {                                                   \
    uint32_t _m = (addr), _p = (uint32_t)(phv), _d;                                 \
    asm volatile("{\n\t.reg .pred p;\n\t"                                           \
        "mbarrier.try_wait.parity.acquire.cta.shared::cta.b64 p, [%1], %2;\n\t"     \
        "selp.b32 %0,1,0,p;\n\t}" : "=r"(_d) : "r"(_m), "r"(_p) : "memory");        \
    if (!_d) {                                                                      \
        asm volatile("{\n\t.reg .pred P1;\n\t"                                      \
        "WL_%=:\n\t"                                                                \
        "mbarrier.try_wait.parity.acquire.cta.shared::cta.b64 P1, [%0], %1, 0x989680;\n\t" \
        "@P1 bra.uni WD_%=;\n\t"                                                    \
        "bra.uni WL_%=;\n\t"                                                        \
        "WD_%=:\n\t}" :: "r"(_m), "r"(_p) : "memory");                              \
    } } while (0)

#define LD32X32(r, ta)                                                              \
    asm volatile("tcgen05.ld.sync.aligned.32x32b.x32.b32 "                          \
        "{%0, %1, %2, %3, %4, %5, %6, %7, %8, %9, %10, %11, %12, %13, %14, %15, "   \
        " %16, %17, %18, %19, %20, %21, %22, %23, %24, %25, %26, %27, %28, %29, %30, %31}, [%32];" \
        : "=r"((r)[0]),"=r"((r)[1]),"=r"((r)[2]),"=r"((r)[3]),                      \
          "=r"((r)[4]),"=r"((r)[5]),"=r"((r)[6]),"=r"((r)[7]),                      \
          "=r"((r)[8]),"=r"((r)[9]),"=r"((r)[10]),"=r"((r)[11]),                    \
          "=r"((r)[12]),"=r"((r)[13]),"=r"((r)[14]),"=r"((r)[15]),                  \
          "=r"((r)[16]),"=r"((r)[17]),"=r"((r)[18]),"=r"((r)[19]),                  \
          "=r"((r)[20]),"=r"((r)[21]),"=r"((r)[22]),"=r"((r)[23]),                  \
          "=r"((r)[24]),"=r"((r)[25]),"=r"((r)[26]),"=r"((r)[27]),                  \
          "=r"((r)[28]),"=r"((r)[29]),"=r"((r)[30]),"=r"((r)[31])                   \
        : "r"(ta))

#define SWZ64(o) ((o) ^ (((o) >> 3) & 0x30))
#endif  // TCGEN05_OK

// Stage (M=256, K=32): Ahi 16K | Alo 16K | Bhi 16K | Blo 16K = 64K; 3 stages.
#define STG_BYTES   65536
#define A_LO_OFF    16384
#define B_HI_OFF    32768
#define B_LO_OFF    49152
#define A1_OFF      8192        // rows 128..255 within an A matrix (128*64B)
#define SMEM_DYN    (2048 + NSTAGE*STG_BYTES)   // 198656

// ---------------------------------------------------------------------------
// W transpose + split
// ---------------------------------------------------------------------------
__global__ __launch_bounds__(256)
void wt_kernel(const float* __restrict__ W) {
    __shared__ float t[32][33];
    int h0 = blockIdx.y * 32, d0 = blockIdx.x * 32;
    int x = threadIdx.x & 31, y = threadIdx.x >> 5;
#pragma unroll
    for (int i = 0; i < 32; i += 8)
        t[y + i][x] = W[(size_t)(h0 + y + i) * HDIM + d0 + x];
    __syncthreads();
#pragma unroll
    for (int i = 0; i < 32; i += 8) {
        float v = t[x][y + i];
        uint32_t u = __float_as_uint(v);
        size_t off = (size_t)(d0 + y + i) * HDIM + h0 + x;
        g_Wth[off] = __ushort_as_bfloat16((unsigned short)(u >> 16));
        g_Wtl[off] = __float2bfloat16(v - __uint_as_float(u & 0xFFFF0000u));
    }
}

// ---------------------------------------------------------------------------
// fp32 -> bf16 hi/lo splits (HBM-bound)
// ---------------------------------------------------------------------------
__device__ __forceinline__ void split8(const float* src, __nv_bfloat16* dhi,
                                       __nv_bfloat16* dlo, size_t base) {
    float4 a = *(const float4*)(src + base);
    float4 b = *(const float4*)(src + base + 4);
    uint4 hi, lo;
    hi.x = pack_hi2(a.x, a.y); hi.y = pack_hi2(a.z, a.w);
    hi.z = pack_hi2(b.x, b.y); hi.w = pack_hi2(b.z, b.w);
    lo.x = pack_lo2(a.x, a.y); lo.y = pack_lo2(a.z, a.w);
    lo.z = pack_lo2(b.x, b.y); lo.w = pack_lo2(b.z, b.w);
    *(uint4*)((char*)dhi + base * 2) = hi;
    *(uint4*)((char*)dlo + base * 2) = lo;
}
__global__ __launch_bounds__(256)
void split_h_kernel(const float* __restrict__ H) {
    split8(H, g_Hhi, g_Hlo, ((size_t)blockIdx.x * 256 + threadIdx.x) * 8);
}
__global__ __launch_bounds__(256)
void split_s_kernel(const float* __restrict__ S) {
    split8(S, g_Shi, g_Slo, ((size_t)blockIdx.x * 256 + threadIdx.x) * 8);
}

#if TCGEN05_OK
// ---------------------------------------------------------------------------
// GEMM mainloop: C_tmem[256x256] = A[256,512] . B[256,512]^T  (bf16x3)
// M=256 via two M=128 dispatches into D0 (cols 0-255) and D1 (cols 256-511).
// 16 chunks of K=32, 3 smem stages of 64KB, cp.async 2 chunks ahead.
// load(c+2) reuses the stage of chunk c-1, guarded by MMA(c-1) which was
// issued one full iteration earlier (drained; no serialization).
// ---------------------------------------------------------------------------
__device__ __forceinline__ uint32_t gemm_mainloop(
    uint32_t sb, uint32_t db,
    const __nv_bfloat16* ahi, const __nv_bfloat16* alo, size_t arow0,
    const __nv_bfloat16* bhi, const __nv_bfloat16* blo, size_t brow0) {
    int tid = threadIdx.x, wid = tid >> 5;

    if (wid == 0)
        asm volatile("tcgen05.alloc.cta_group::1.sync.aligned.shared::cta.b32 [%0], %1;"
                     :: "r"(sb + 32), "r"(512u) : "memory");
    if (tid == 0) {
#pragma unroll
        for (int s = 0; s < NSTAGE; s++) MBAR_INIT(sb + s * 8, 1u);
    }
    __syncthreads();
    uint32_t td;
    asm volatile("ld.shared.b32 %0, [%1];" : "=r"(td) : "r"(sb + 32));

    auto load_chunk = [&](int c) {
        uint32_t ba = db + (c % 3) * STG_BYTES;
        int k0 = c * 32;
#pragma unroll
        for (int t = 0; t < 4; t++) {              // A: 256 rows x 4 x 16B
            int it = tid + 256 * t;
            int r = it >> 2, g = it & 3;
            int o = SWZ64(r * 64 + g * 16);
            size_t src = (arow0 + r) * HDIM + k0 + (g << 3);
            CPA16(ba + o,            ahi + src);
            CPA16(ba + A_LO_OFF + o, alo + src);
        }
#pragma unroll
        for (int t = 0; t < 4; t++) {              // B: 256 rows x 4 x 16B
            int it = tid + 256 * t;
            int r = it >> 2, g = it & 3;
            int o = SWZ64(r * 64 + g * 16);
            size_t src = (brow0 + r) * HDIM + k0 + (g << 3);
            CPA16(ba + B_HI_OFF + o, bhi + src);
            CPA16(ba + B_LO_OFF + o, blo + src);
        }
        CPA_COMMIT();
    };

    load_chunk(0);
    load_chunk(1);

#pragma unroll
    for (int c = 0; c < NCHUNK; c++) {
        if (c <= 14) CPA_WAIT(1); else CPA_WAIT(0);
        asm volatile("fence.proxy.async.shared::cta;" ::: "memory");
        __syncthreads();
        if (wid == 0 && elect_one()) {
            uint32_t ba = db + (c % 3) * STG_BYTES;
            uint64_t a0h = make_desc64(ba),            a1h = make_desc64(ba + A1_OFF);
            uint64_t a0l = make_desc64(ba + A_LO_OFF), a1l = make_desc64(ba + A_LO_OFF + A1_OFF);
            uint64_t bh  = make_desc64(ba + B_HI_OFF), bl  = make_desc64(ba + B_LO_OFF);
            uint32_t en0 = (c == 0) ? 0u : 1u;
#pragma unroll
            for (int ks = 0; ks < 2; ks++) {
                uint32_t en = (ks == 0) ? en0 : 1u;
                mma_ss_f16(td,       a0h + 2 * ks, bh + 2 * ks, IDESC_128x256, en);
                mma_ss_f16(td + 256, a1h + 2 * ks, bh + 2 * ks, IDESC_128x256, en);
            }
#pragma unroll
            for (int ks = 0; ks < 2; ks++) {
                mma_ss_f16(td,       a0h + 2 * ks, bl + 2 * ks, IDESC_128x256, 1u);
                mma_ss_f16(td + 256, a1h + 2 * ks, bl + 2 * ks, IDESC_128x256, 1u);
            }
#pragma unroll
            for (int ks = 0; ks < 2; ks++) {
                mma_ss_f16(td,       a0l + 2 * ks, bh + 2 * ks, IDESC_128x256, 1u);
                mma_ss_f16(td + 256, a1l + 2 * ks, bh + 2 * ks, IDESC_128x256, 1u);
            }
            asm volatile(
                "tcgen05.commit.cta_group::1.mbarrier::arrive::one.shared::cluster.b64 [%0];"
                :: "r"(sb + (c % 3) * 8) : "memory");
        }
        if (c + 2 < NCHUNK) {
            if (c >= 1)
                MBAR_WAIT(sb + ((c - 1) % 3) * 8, ((c - 1) / 3) & 1);
            load_chunk(c + 2);
        }
    }
    // last chunk 15: stage 0, completion index 5 -> parity 1
    MBAR_WAIT(sb + 0 * 8, 1);
    asm volatile("tcgen05.fence::after_thread_sync;" ::: "memory");
    return td;
}
__device__ __forceinline__ void gemm_cleanup(uint32_t td) {
    __syncthreads();
    if ((threadIdx.x >> 5) == 0)
        asm volatile("tcgen05.dealloc.cta_group::1.sync.aligned.b32 %0, %1;"
                     :: "r"(td), "r"(512u));
}
#endif  // TCGEN05_OK

// ---------------------------------------------------------------------------
// K1: Q = S @ W  (tile 256x256), epilogue -> Q hi/lo bf16
// ---------------------------------------------------------------------------
__global__ __launch_bounds__(256, 1)
void k1_kernel() {
#if TCGEN05_OK
    extern __shared__ char sm[];
    uint32_t sb = smem_u32(sm);
    uint32_t db = (sb + 64 + 1023) & ~1023u;
    int wid = threadIdx.x >> 5, lane = threadIdx.x & 31;
    int m0 = blockIdx.y * 256, n0 = blockIdx.x * 256;

    uint32_t td = gemm_mainloop(sb, db, g_Shi, g_Slo, (size_t)m0,
                                g_Wth, g_Wtl, (size_t)n0);

    // D0 cols 0-255 = rows m0+0..127 (warps 0-3); D1 cols 256-511 = rows +128 (warps 4-7)
    int half = wid >> 2;
    int mrow = m0 + ((wid & 3) << 5) + lane + half * 128;
    uint32_t dbase = half ? 256u : 0u;
#pragma unroll
    for (int itn = 0; itn < 8; itn++) {
        uint32_t dr[32];
        LD32X32(dr, td + dbase + itn * 32);
        asm volatile("tcgen05.wait::ld.sync.aligned;" ::: "memory");
#pragma unroll
        for (int g = 0; g < 4; g++) {
            float q0 = __uint_as_float(dr[g * 8 + 0]), q1 = __uint_as_float(dr[g * 8 + 1]);
            float q2 = __uint_as_float(dr[g * 8 + 2]), q3 = __uint_as_float(dr[g * 8 + 3]);
            float q4 = __uint_as_float(dr[g * 8 + 4]), q5 = __uint_as_float(dr[g * 8 + 5]);
            float q6 = __uint_as_float(dr[g * 8 + 6]), q7 = __uint_as_float(dr[g * 8 + 7]);
            uint4 hi, lo;
            hi.x = pack_hi2(q0, q1); hi.y = pack_hi2(q2, q3);
            hi.z = pack_hi2(q4, q5); hi.w = pack_hi2(q6, q7);
            lo.x = pack_lo2(q0, q1); lo.y = pack_lo2(q2, q3);
            lo.z = pack_lo2(q4, q5); lo.w = pack_lo2(q6, q7);
            size_t off = (size_t)mrow * HDIM + n0 + itn * 32 + g * 8;
            *(uint4*)(g_Qhi + off) = hi;
            *(uint4*)(g_Qlo + off) = lo;
        }
    }
    gemm_cleanup(td);
#endif
}

// ---------------------------------------------------------------------------
// K2: E[b] = Q[b] @ hist[b]^T  (tile 256x256), epilogue -> fp32 energies
// (bias dropped: softmax is shift-invariant per row)
// ---------------------------------------------------------------------------
__global__ __launch_bounds__(256, 1)
void k2_kernel(float* __restrict__ out) {
#if TCGEN05_OK
    extern __shared__ char sm[];
    uint32_t sb = smem_u32(sm);
    uint32_t db = (sb + 64 + 1023) & ~1023u;
    int wid = threadIdx.x >> 5, lane = threadIdx.x & 31;
    int bb = blockIdx.z;
    int m0 = blockIdx.y * 256, n0 = blockIdx.x * 256;
    float* C = out + (size_t)bb * SSTATE * SSEQ;

    uint32_t td = gemm_mainloop(sb, db,
                                g_Qhi, g_Qlo, (size_t)bb * SSTATE + m0,
                                g_Hhi, g_Hlo, (size_t)bb * SSEQ + n0);

    int half = wid >> 2;
    int mloc = ((wid & 3) << 5) + lane + half * 128;
    uint32_t dbase = half ? 256u : 0u;
#pragma unroll
    for (int itn = 0; itn < 8; itn++) {
        uint32_t dr[32];
        LD32X32(dr, td + dbase + itn * 32);
        asm volatile("tcgen05.wait::ld.sync.aligned;" ::: "memory");
        float* crow = C + (size_t)(m0 + mloc) * SSEQ + n0 + itn * 32;
#pragma unroll
        for (int g = 0; g < 8; g++) {
            *(float4*)(crow + g * 4) = make_float4(
                __uint_as_float(dr[g * 4 + 0]), __uint_as_float(dr[g * 4 + 1]),
                __uint_as_float(dr[g * 4 + 2]), __uint_as_float(dr[g * 4 + 3]));
        }
    }
    gemm_cleanup(td);
#endif
}

// ---------------------------------------------------------------------------
// softmax over rows of 2048 (75% of HBM peak — unchanged)
// ---------------------------------------------------------------------------
__device__ __forceinline__ float fexp_neg(float x) {
    float t = x * 1.4426950408889634f;
    t = fmaxf(t, -250.0f);
    float fi = t + 12582912.0f;
    int i = __float_as_int(fi) - 0x4B400000;
    float f = t - (fi - 12582912.0f);
    float p = 1.5404e-4f;
    p = fmaf(p, f, 1.33336e-3f);
    p = fmaf(p, f, 9.61813e-3f);
    p = fmaf(p, f, 5.55041e-2f);
    p = fmaf(p, f, 2.40226513e-1f);
    p = fmaf(p, f, 6.93147182e-1f);
    p = fmaf(p, f, 1.0f);
    int i1 = i >> 1;
    int i2 = i - i1;
    return p * __int_as_float((i1 + 127) << 23) * __int_as_float((i2 + 127) << 23);
}

__global__ __launch_bounds__(256)
void softmax_kernel(float* __restrict__ data) {
    __shared__ float red[8];
    size_t row = blockIdx.x;
    float4* p = (float4*)(data + row * SSEQ);
    int tid = threadIdx.x;
    int lane = tid & 31, warp = tid >> 5;

    float4 v0 = p[tid];
    float4 v1 = p[tid + 256];
    float m = fmaxf(fmaxf(fmaxf(v0.x, v0.y), fmaxf(v0.z, v0.w)),
                    fmaxf(fmaxf(v1.x, v1.y), fmaxf(v1.z, v1.w)));
#pragma unroll
    for (int off = 16; off; off >>= 1) m = fmaxf(m, __shfl_xor_sync(0xffffffffu, m, off));
    if (lane == 0) red[warp] = m;
    __syncthreads();
    float gm = red[0];
#pragma unroll
    for (int w = 1; w < 8; w++) gm = fmaxf(gm, red[w]);
    __syncthreads();

    float e[8];
    e[0] = fexp_neg(v0.x - gm); e[1] = fexp_neg(v0.y - gm);
    e[2] = fexp_neg(v0.z - gm); e[3] = fexp_neg(v0.w - gm);
    e[4] = fexp_neg(v1.x - gm); e[5] = fexp_neg(v1.y - gm);
    e[6] = fexp_neg(v1.z - gm); e[7] = fexp_neg(v1.w - gm);
    float s = ((e[0] + e[1]) + (e[2] + e[3])) + ((e[4] + e[5]) + (e[6] + e[7]));
#pragma unroll
    for (int off = 16; off; off >>= 1) s += __shfl_xor_sync(0xffffffffu, s, off);
    if (lane == 0) red[warp] = s;
    __syncthreads();
    float gs = ((red[0] + red[1]) + (red[2] + red[3])) +
               ((red[4] + red[5]) + (red[6] + red[7]));
    float inv = 1.0f / gs;

    p[tid]       = make_float4(e[0] * inv, e[1] * inv, e[2] * inv, e[3] * inv);
    p[tid + 256] = make_float4(e[4] * inv, e[5] * inv, e[6] * inv, e[7] * inv);
}

// ---------------------------------------------------------------------------
extern "C" void kernel_launch(void* const* d_in, const int* in_sizes, int n_in,
                              void* d_out, int out_size) {
    (void)in_sizes; (void)n_in; (void)out_size;
    const float* S   = (const float*)d_in[0];  // out_state [64,512,512]
    const float* Hst = (const float*)d_in[1];  // history   [64,2048,512]
    const float* W   = (const float*)d_in[2];  // attn_w    [512,512]
    // d_in[3] (attn_b) unused: softmax is shift-invariant per row.
    float* out = (float*)d_out;                // [64,512,2048]

    cudaFuncSetAttribute(k1_kernel, cudaFuncAttributeMaxDynamicSharedMemorySize, SMEM_DYN);
    cudaFuncSetAttribute(k2_kernel, cudaFuncAttributeMaxDynamicSharedMemorySize, SMEM_DYN);

    wt_kernel<<<dim3(16, 16), 256>>>(W);
    split_s_kernel<<<(size_t)MTOT * HDIM / 2048, 256>>>(S);
    split_h_kernel<<<(size_t)B_ * SSEQ * HDIM / 2048, 256>>>(Hst);
    k1_kernel<<<dim3(HDIM / 256, MTOT / 256), 256, SMEM_DYN>>>();          // (2, 128)
    k2_kernel<<<dim3(SSEQ / 256, SSTATE / 256, B_), 256, SMEM_DYN>>>(out); // (8, 2, 64)
    softmax_kernel<<<MTOT, 256>>>(out);
}

// round 16
// speedup vs baseline: 1.4899x; 1.0092x over previous
#include <cuda_runtime.h>
#include <cuda_bf16.h>
#include <cstdint>

#define B_      64
#define SSTATE  512
#define SSEQ    2048
#define HDIM    512
#define MTOT    (B_*SSTATE)
#define NCHUNK  16          // K = 512 in chunks of 32
#define NSTAGE  3

#if defined(__CUDA_ARCH_FEAT_SM103_ALL) || defined(__CUDA_ARCH_FEAT_SM100_ALL) || defined(__CUDA_ARCH_SPECIFIC__)
#define TCGEN05_OK 1
#else
#define TCGEN05_OK 0
#endif

// idesc kind::f16 bf16 x bf16 -> fp32, M=128 (per dispatch), N=256
#define IDESC_128x256 \
    ((1u << 4) | (1u << 7) | (1u << 10) | ((256u / 8) << 17) | ((128u / 16) << 24))

// scratch (static device globals)
__device__ __nv_bfloat16 g_Qhi[(size_t)MTOT * HDIM];
__device__ __nv_bfloat16 g_Qlo[(size_t)MTOT * HDIM];
__device__ __nv_bfloat16 g_Shi[(size_t)MTOT * HDIM];
__device__ __nv_bfloat16 g_Slo[(size_t)MTOT * HDIM];
__device__ __nv_bfloat16 g_Hhi[(size_t)B_ * SSEQ * HDIM];
__device__ __nv_bfloat16 g_Hlo[(size_t)B_ * SSEQ * HDIM];
__device__ __nv_bfloat16 g_Wth[HDIM * HDIM];
__device__ __nv_bfloat16 g_Wtl[HDIM * HDIM];

// ---- split helpers (truncate-hi + exact remainder) ----
__device__ __forceinline__ uint32_t pack_hi2(float x0, float x1) {
    return (__float_as_uint(x0) >> 16) | (__float_as_uint(x1) & 0xFFFF0000u);
}
__device__ __forceinline__ uint32_t pack_lo2(float x0, float x1) {
    float r0 = x0 - __uint_as_float(__float_as_uint(x0) & 0xFFFF0000u);
    float r1 = x1 - __uint_as_float(__float_as_uint(x1) & 0xFFFF0000u);
    uint32_t r;
    asm("cvt.rn.bf16x2.f32 %0, %1, %2;" : "=r"(r) : "f"(r1), "f"(r0));
    return r;
}
__device__ __forceinline__ void split8(const float* src, __nv_bfloat16* dhi,
                                       __nv_bfloat16* dlo, size_t base) {
    float4 a = *(const float4*)(src + base);
    float4 b = *(const float4*)(src + base + 4);
    uint4 hi, lo;
    hi.x = pack_hi2(a.x, a.y); hi.y = pack_hi2(a.z, a.w);
    hi.z = pack_hi2(b.x, b.y); hi.w = pack_hi2(b.z, b.w);
    lo.x = pack_lo2(a.x, a.y); lo.y = pack_lo2(a.z, a.w);
    lo.z = pack_lo2(b.x, b.y); lo.w = pack_lo2(b.z, b.w);
    *(uint4*)((char*)dhi + base * 2) = hi;
    *(uint4*)((char*)dlo + base * 2) = lo;
}

#if TCGEN05_OK
__device__ __forceinline__ uint32_t smem_u32(const void* p) {
    uint32_t a;
    asm("{ .reg .u64 t; cvta.to.shared.u64 t, %1; cvt.u32.u64 %0, t; }" : "=r"(a) : "l"(p));
    return a;
}
__device__ __forceinline__ uint32_t elect_one() {
    uint32_t p;
    asm volatile("{ .reg .pred p; elect.sync _|p, 0xFFFFFFFF; selp.b32 %0,1,0,p; }" : "=r"(p));
    return p;
}
// SW64 descriptor: layout=4, Blackwell version=1, SBO=32, LBO=1 (HW-verified)
__device__ __forceinline__ uint64_t make_desc64(uint32_t addr) {
    const uint64_t base = (uint64_t(4) << 61) | (uint64_t(1) << 46) |
                          (uint64_t(32) << 32) | (uint64_t(1) << 16);
    return base | ((uint64_t)(addr >> 4) & 0x3FFF);
}
__device__ __forceinline__ void mma_ss_f16(uint32_t d, uint64_t a, uint64_t b,
                                           uint32_t idesc, uint32_t en) {
    asm volatile(
        "{\n\t.reg .pred p;\n\tsetp.ne.u32 p, %4, 0;\n\t"
        "tcgen05.mma.cta_group::1.kind::f16 [%0], %1, %2, %3, {%5,%5,%5,%5}, p;\n\t}"
        :: "r"(d), "l"(a), "l"(b), "r"(idesc), "r"(en), "r"(0u) : "memory");
}

#define CPA16(dst_u32, src_ptr) \
    asm volatile("cp.async.cg.shared.global [%0], [%1], 16;" \
                 :: "r"(dst_u32), "l"(src_ptr) : "memory")
#define CPA_COMMIT()  asm volatile("cp.async.commit_group;" ::: "memory")
#define CPA_WAIT(n)   asm volatile("cp.async.wait_group %0;" :: "n"(n) : "memory")

#define MBAR_INIT(addr, cnt) \
    asm volatile("mbarrier.init.shared.b64 [%0], %1;" :: "r"(addr), "r"(cnt) : "memory")
#define MBAR_WAIT(addr, phv) do {                                                   \
    uint32_t _m = (addr), _p = (uint32_t)(phv), _d;                                 \
    asm volatile("{\n\t.reg .pred p;\n\t"                                           \
        "mbarrier.try_wait.parity.acquire.cta.shared::cta.b64 p, [%1], %2;\n\t"     \
        "selp.b32 %0,1,0,p;\n\t}" : "=r"(_d) : "r"(_m), "r"(_p) : "memory");        \
    if (!_d) {                                                                      \
        asm volatile("{\n\t.reg .pred P1;\n\t"                                      \
        "WL_%=:\n\t"                                                                \
        "mbarrier.try_wait.parity.acquire.cta.shared::cta.b64 P1, [%0], %1, 0x989680;\n\t" \
        "@P1 bra.uni WD_%=;\n\t"                                                    \
        "bra.uni WL_%=;\n\t"                                                        \
        "WD_%=:\n\t}" :: "r"(_m), "r"(_p) : "memory");                              \
    } } while (0)

#define LD32X32(r, ta)                                                              \
    asm volatile("tcgen05.ld.sync.aligned.32x32b.x32.b32 "                          \
        "{%0, %1, %2, %3, %4, %5, %6, %7, %8, %9, %10, %11, %12, %13, %14, %15, "   \
        " %16, %17, %18, %19, %20, %21, %22, %23, %24, %25, %26, %27, %28, %29, %30, %31}, [%32];" \
        : "=r"((r)[0]),"=r"((r)[1]),"=r"((r)[2]),"=r"((r)[3]),                      \
          "=r"((r)[4]),"=r"((r)[5]),"=r"((r)[6]),"=r"((r)[7]),                      \
          "=r"((r)[8]),"=r"((r)[9]),"=r"((r)[10]),"=r"((r)[11]),                    \
          "=r"((r)[12]),"=r"((r)[13]),"=r"((r)[14]),"=r"((r)[15]),                  \
          "=r"((r)[16]),"=r"((r)[17]),"=r"((r)[18]),"=r"((r)[19]),                  \
          "=r"((r)[20]),"=r"((r)[21]),"=r"((r)[22]),"=r"((r)[23]),                  \
          "=r"((r)[24]),"=r"((r)[25]),"=r"((r)[26]),"=r"((r)[27]),                  \
          "=r"((r)[28]),"=r"((r)[29]),"=r"((r)[30]),"=r"((r)[31])                   \
        : "r"(ta))

#define SWZ64(o) ((o) ^ (((o) >> 3) & 0x30))
#endif  // TCGEN05_OK

// Stage (M=256, K=32): Ahi 16K | Alo 16K | Bhi 16K | Blo 16K = 64K; 3 stages.
#define STG_BYTES   65536
#define A_LO_OFF    16384
#define B_HI_OFF    32768
#define B_LO_OFF    49152
#define A1_OFF      8192        // rows 128..255 within an A matrix (128*64B)
#define SMEM_DYN    (2048 + NSTAGE*STG_BYTES)   // 198656

// ---------------------------------------------------------------------------
// W transpose + split
// ---------------------------------------------------------------------------
__global__ __launch_bounds__(256)
void wt_kernel(const float* __restrict__ W) {
    __shared__ float t[32][33];
    int h0 = blockIdx.y * 32, d0 = blockIdx.x * 32;
    int x = threadIdx.x & 31, y = threadIdx.x >> 5;
#pragma unroll
    for (int i = 0; i < 32; i += 8)
        t[y + i][x] = W[(size_t)(h0 + y + i) * HDIM + d0 + x];
    __syncthreads();
#pragma unroll
    for (int i = 0; i < 32; i += 8) {
        float v = t[x][y + i];
        uint32_t u = __float_as_uint(v);
        size_t off = (size_t)(d0 + y + i) * HDIM + h0 + x;
        g_Wth[off] = __ushort_as_bfloat16((unsigned short)(u >> 16));
        g_Wtl[off] = __float2bfloat16(v - __uint_as_float(u & 0xFFFF0000u));
    }
}

// ---------------------------------------------------------------------------
// S fp32 -> bf16 hi/lo split (k1 GEMM input; must precede k1s)
// ---------------------------------------------------------------------------
__global__ __launch_bounds__(256)
void split_s_kernel(const float* __restrict__ S) {
    split8(S, g_Shi, g_Slo, ((size_t)blockIdx.x * 256 + threadIdx.x) * 8);
}

#if TCGEN05_OK
// ---------------------------------------------------------------------------
// GEMM mainloop: C_tmem[256x256] = A[256,512] . B[256,512]^T  (bf16x3)
// M=256 via two M=128 dispatches into D0 (cols 0-255) and D1 (cols 256-511).
// 16 chunks of K=32, 3 smem stages of 64KB, cp.async 2 chunks ahead.
// load(c+2) reuses the stage of chunk c-1, guarded by MMA(c-1) issued a full
// iteration earlier (drained; no serialization).
// ---------------------------------------------------------------------------
__device__ __forceinline__ uint32_t gemm_mainloop(
    uint32_t sb, uint32_t db,
    const __nv_bfloat16* ahi, const __nv_bfloat16* alo, size_t arow0,
    const __nv_bfloat16* bhi, const __nv_bfloat16* blo, size_t brow0) {
    int tid = threadIdx.x, wid = tid >> 5;

    if (wid == 0)
        asm volatile("tcgen05.alloc.cta_group::1.sync.aligned.shared::cta.b32 [%0], %1;"
                     :: "r"(sb + 32), "r"(512u) : "memory");
    if (tid == 0) {
#pragma unroll
        for (int s = 0; s < NSTAGE; s++) MBAR_INIT(sb + s * 8, 1u);
    }
    __syncthreads();
    uint32_t td;
    asm volatile("ld.shared.b32 %0, [%1];" : "=r"(td) : "r"(sb + 32));

    auto load_chunk = [&](int c) {
        uint32_t ba = db + (c % 3) * STG_BYTES;
        int k0 = c * 32;
#pragma unroll
        for (int t = 0; t < 4; t++) {              // A: 256 rows x 4 x 16B
            int it = tid + 256 * t;
            int r = it >> 2, g = it & 3;
            int o = SWZ64(r * 64 + g * 16);
            size_t src = (arow0 + r) * HDIM + k0 + (g << 3);
            CPA16(ba + o,            ahi + src);
            CPA16(ba + A_LO_OFF + o, alo + src);
        }
#pragma unroll
        for (int t = 0; t < 4; t++) {              // B: 256 rows x 4 x 16B
            int it = tid + 256 * t;
            int r = it >> 2, g = it & 3;
            int o = SWZ64(r * 64 + g * 16);
            size_t src = (brow0 + r) * HDIM + k0 + (g << 3);
            CPA16(ba + B_HI_OFF + o, bhi + src);
            CPA16(ba + B_LO_OFF + o, blo + src);
        }
        CPA_COMMIT();
    };

    load_chunk(0);
    load_chunk(1);

#pragma unroll
    for (int c = 0; c < NCHUNK; c++) {
        if (c <= 14) CPA_WAIT(1); else CPA_WAIT(0);
        asm volatile("fence.proxy.async.shared::cta;" ::: "memory");
        __syncthreads();
        if (wid == 0 && elect_one()) {
            uint32_t ba = db + (c % 3) * STG_BYTES;
            uint64_t a0h = make_desc64(ba),            a1h = make_desc64(ba + A1_OFF);
            uint64_t a0l = make_desc64(ba + A_LO_OFF), a1l = make_desc64(ba + A_LO_OFF + A1_OFF);
            uint64_t bh  = make_desc64(ba + B_HI_OFF), bl  = make_desc64(ba + B_LO_OFF);
            uint32_t en0 = (c == 0) ? 0u : 1u;
#pragma unroll
            for (int ks = 0; ks < 2; ks++) {
                uint32_t en = (ks == 0) ? en0 : 1u;
                mma_ss_f16(td,       a0h + 2 * ks, bh + 2 * ks, IDESC_128x256, en);
                mma_ss_f16(td + 256, a1h + 2 * ks, bh + 2 * ks, IDESC_128x256, en);
            }
#pragma unroll
            for (int ks = 0; ks < 2; ks++) {
                mma_ss_f16(td,       a0h + 2 * ks, bl + 2 * ks, IDESC_128x256, 1u);
                mma_ss_f16(td + 256, a1h + 2 * ks, bl + 2 * ks, IDESC_128x256, 1u);
            }
#pragma unroll
            for (int ks = 0; ks < 2; ks++) {
                mma_ss_f16(td,       a0l + 2 * ks, bh + 2 * ks, IDESC_128x256, 1u);
                mma_ss_f16(td + 256, a1l + 2 * ks, bh + 2 * ks, IDESC_128x256, 1u);
            }
            asm volatile(
                "tcgen05.commit.cta_group::1.mbarrier::arrive::one.shared::cluster.b64 [%0];"
                :: "r"(sb + (c % 3) * 8) : "memory");
        }
        if (c + 2 < NCHUNK) {
            if (c >= 1)
                MBAR_WAIT(sb + ((c - 1) % 3) * 8, ((c - 1) / 3) & 1);
            load_chunk(c + 2);
        }
    }
    // last chunk 15: stage 0, completion index 5 -> parity 1
    MBAR_WAIT(sb + 0 * 8, 1);
    asm volatile("tcgen05.fence::after_thread_sync;" ::: "memory");
    return td;
}
__device__ __forceinline__ void gemm_cleanup(uint32_t td) {
    __syncthreads();
    if ((threadIdx.x >> 5) == 0)
        asm volatile("tcgen05.dealloc.cta_group::1.sync.aligned.b32 %0, %1;"
                     :: "r"(td), "r"(512u));
}
#endif  // TCGEN05_OK

// ---------------------------------------------------------------------------
// k1s: heterogeneous grid.
//   blocks [0,256):    Q = S @ W tile 256x256 (tensor-bound, DRAM-light)
//   blocks [256,2304): history fp32 -> bf16 hi/lo split (HBM-bound)
// No dependency between the two paths: GEMM reads S/W splits (prior kernels),
// split path writes g_Hhi/g_Hlo read only by k2 (next kernel).
// ---------------------------------------------------------------------------
__global__ __launch_bounds__(256, 1)
void k1s_kernel(const float* __restrict__ Hst) {
#if TCGEN05_OK
    if (blockIdx.x >= 256) {
        // ---- history split path: 2048 CTAs x 16 segs x 2048 floats ----
        size_t sbid = blockIdx.x - 256;
#pragma unroll
        for (int it = 0; it < 16; it++) {
            size_t base = (sbid * 16 + it) * 2048 + (size_t)threadIdx.x * 8;
            split8(Hst, g_Hhi, g_Hlo, base);
        }
        return;
    }
    // ---- GEMM path ----
    extern __shared__ char sm[];
    uint32_t sb = smem_u32(sm);
    uint32_t db = (sb + 64 + 1023) & ~1023u;
    int wid = threadIdx.x >> 5, lane = threadIdx.x & 31;
    int m0 = (blockIdx.x >> 1) * 256, n0 = (blockIdx.x & 1) * 256;

    uint32_t td = gemm_mainloop(sb, db, g_Shi, g_Slo, (size_t)m0,
                                g_Wth, g_Wtl, (size_t)n0);

    // D0 cols 0-255 = rows m0+0..127 (warps 0-3); D1 cols 256-511 = rows +128
    int half = wid >> 2;
    int mrow = m0 + ((wid & 3) << 5) + lane + half * 128;
    uint32_t dbase = half ? 256u : 0u;
#pragma unroll
    for (int itn = 0; itn < 8; itn++) {
        uint32_t dr[32];
        LD32X32(dr, td + dbase + itn * 32);
        asm volatile("tcgen05.wait::ld.sync.aligned;" ::: "memory");
#pragma unroll
        for (int g = 0; g < 4; g++) {
            float q0 = __uint_as_float(dr[g * 8 + 0]), q1 = __uint_as_float(dr[g * 8 + 1]);
            float q2 = __uint_as_float(dr[g * 8 + 2]), q3 = __uint_as_float(dr[g * 8 + 3]);
            float q4 = __uint_as_float(dr[g * 8 + 4]), q5 = __uint_as_float(dr[g * 8 + 5]);
            float q6 = __uint_as_float(dr[g * 8 + 6]), q7 = __uint_as_float(dr[g * 8 + 7]);
            uint4 hi, lo;
            hi.x = pack_hi2(q0, q1); hi.y = pack_hi2(q2, q3);
            hi.z = pack_hi2(q4, q5); hi.w = pack_hi2(q6, q7);
            lo.x = pack_lo2(q0, q1); lo.y = pack_lo2(q2, q3);
            lo.z = pack_lo2(q4, q5); lo.w = pack_lo2(q6, q7);
            size_t off = (size_t)mrow * HDIM + n0 + itn * 32 + g * 8;
            *(uint4*)(g_Qhi + off) = hi;
            *(uint4*)(g_Qlo + off) = lo;
        }
    }
    gemm_cleanup(td);
#endif
}

// ---------------------------------------------------------------------------
// K2: E[b] = Q[b] @ hist[b]^T  (tile 256x256), epilogue -> fp32 energies
// (bias dropped: softmax is shift-invariant per row)
// ---------------------------------------------------------------------------
__global__ __launch_bounds__(256, 1)
void k2_kernel(float* __restrict__ out) {
#if TCGEN05_OK
    extern __shared__ char sm[];
    uint32_t sb = smem_u32(sm);
    uint32_t db = (sb + 64 + 1023) & ~1023u;
    int wid = threadIdx.x >> 5, lane = threadIdx.x & 31;
    int bb = blockIdx.z;
    int m0 = blockIdx.y * 256, n0 = blockIdx.x * 256;
    float* C = out + (size_t)bb * SSTATE * SSEQ;

    uint32_t td = gemm_mainloop(sb, db,
                                g_Qhi, g_Qlo, (size_t)bb * SSTATE + m0,
                                g_Hhi, g_Hlo, (size_t)bb * SSEQ + n0);

    int half = wid >> 2;
    int mloc = ((wid & 3) << 5) + lane + half * 128;
    uint32_t dbase = half ? 256u : 0u;
#pragma unroll
    for (int itn = 0; itn < 8; itn++) {
        uint32_t dr[32];
        LD32X32(dr, td + dbase + itn * 32);
        asm volatile("tcgen05.wait::ld.sync.aligned;" ::: "memory");
        float* crow = C + (size_t)(m0 + mloc) * SSEQ + n0 + itn * 32;
#pragma unroll
        for (int g = 0; g < 8; g++) {
            *(float4*)(crow + g * 4) = make_float4(
                __uint_as_float(dr[g * 4 + 0]), __uint_as_float(dr[g * 4 + 1]),
                __uint_as_float(dr[g * 4 + 2]), __uint_as_float(dr[g * 4 + 3]));
        }
    }
    gemm_cleanup(td);
#endif
}

// ---------------------------------------------------------------------------
// softmax over rows of 2048 (75% of HBM peak — unchanged)
// ---------------------------------------------------------------------------
__device__ __forceinline__ float fexp_neg(float x) {
    float t = x * 1.4426950408889634f;
    t = fmaxf(t, -250.0f);
    float fi = t + 12582912.0f;
    int i = __float_as_int(fi) - 0x4B400000;
    float f = t - (fi - 12582912.0f);
    float p = 1.5404e-4f;
    p = fmaf(p, f, 1.33336e-3f);
    p = fmaf(p, f, 9.61813e-3f);
    p = fmaf(p, f, 5.55041e-2f);
    p = fmaf(p, f, 2.40226513e-1f);
    p = fmaf(p, f, 6.93147182e-1f);
    p = fmaf(p, f, 1.0f);
    int i1 = i >> 1;
    int i2 = i - i1;
    return p * __int_as_float((i1 + 127) << 23) * __int_as_float((i2 + 127) << 23);
}

__global__ __launch_bounds__(256)
void softmax_kernel(float* __restrict__ data) {
    __shared__ float red[8];
    size_t row = blockIdx.x;
    float4* p = (float4*)(data + row * SSEQ);
    int tid = threadIdx.x;
    int lane = tid & 31, warp = tid >> 5;

    float4 v0 = p[tid];
    float4 v1 = p[tid + 256];
    float m = fmaxf(fmaxf(fmaxf(v0.x, v0.y), fmaxf(v0.z, v0.w)),
                    fmaxf(fmaxf(v1.x, v1.y), fmaxf(v1.z, v1.w)));
#pragma unroll
    for (int off = 16; off; off >>= 1) m = fmaxf(m, __shfl_xor_sync(0xffffffffu, m, off));
    if (lane == 0) red[warp] = m;
    __syncthreads();
    float gm = red[0];
#pragma unroll
    for (int w = 1; w < 8; w++) gm = fmaxf(gm, red[w]);
    __syncthreads();

    float e[8];
    e[0] = fexp_neg(v0.x - gm); e[1] = fexp_neg(v0.y - gm);
    e[2] = fexp_neg(v0.z - gm); e[3] = fexp_neg(v0.w - gm);
    e[4] = fexp_neg(v1.x - gm); e[5] = fexp_neg(v1.y - gm);
    e[6] = fexp_neg(v1.z - gm); e[7] = fexp_neg(v1.w - gm);
    float s = ((e[0] + e[1]) + (e[2] + e[3])) + ((e[4] + e[5]) + (e[6] + e[7]));
#pragma unroll
    for (int off = 16; off; off >>= 1) s += __shfl_xor_sync(0xffffffffu, s, off);
    if (lane == 0) red[warp] = s;
    __syncthreads();
    float gs = ((red[0] + red[1]) + (red[2] + red[3])) +
               ((red[4] + red[5]) + (red[6] + red[7]));
    float inv = 1.0f / gs;

    p[tid]       = make_float4(e[0] * inv, e[1] * inv, e[2] * inv, e[3] * inv);
    p[tid + 256] = make_float4(e[4] * inv, e[5] * inv, e[6] * inv, e[7] * inv);
}

// ---------------------------------------------------------------------------
extern "C" void kernel_launch(void* const* d_in, const int* in_sizes, int n_in,
                              void* d_out, int out_size) {
    (void)in_sizes; (void)n_in; (void)out_size;
    const float* S   = (const float*)d_in[0];  // out_state [64,512,512]
    const float* Hst = (const float*)d_in[1];  // history   [64,2048,512]
    const float* W   = (const float*)d_in[2];  // attn_w    [512,512]
    // d_in[3] (attn_b) unused: softmax is shift-invariant per row.
    float* out = (float*)d_out;                // [64,512,2048]

    cudaFuncSetAttribute(k1s_kernel, cudaFuncAttributeMaxDynamicSharedMemorySize, SMEM_DYN);
    cudaFuncSetAttribute(k2_kernel,  cudaFuncAttributeMaxDynamicSharedMemorySize, SMEM_DYN);

    wt_kernel<<<dim3(16, 16), 256>>>(W);
    split_s_kernel<<<(size_t)MTOT * HDIM / 2048, 256>>>(S);
    k1s_kernel<<<256 + 2048, 256, SMEM_DYN>>>(Hst);   // GEMM tiles + H split fused
    k2_kernel<<<dim3(SSEQ / 256, SSTATE / 256, B_), 256, SMEM_DYN>>>(out);
    softmax_kernel<<<MTOT, 256>>>(out);
}